// round 12
// baseline (speedup 1.0000x reference)
#include <cuda_runtime.h>
#include <math.h>

// Chamfer loss, B=4, C=3, Np=Ng=8192. R12 = R11 single-launch design with
// TPQ=64 / RP=4: 512 blocks (~3.5/SM), __launch_bounds__(256,4) -> up to 32
// warps/SM (was 16). Evidence: R7..R11 profiles pin issue=63% at occ=21%
// (grid-capped); more resident warps is the remaining lever.
//  - col-min as atomicMax of (0x7f7fffff - bits): zero-init == FLT_MAX (no init kernel)
//  - row partials in fixed-point u64 (integer adds commute => deterministic)
//  - last block (ticket) runs a vectorized finalize and resets globals.

#define BATCH   4
#define NPT     8192
#define TPQ     64                       // predict points per block
#define TGQ     128                      // gt points per stage
#define NSTAGES (NPT / TGQ)              // 64
#define NTH     256                      // 16 (g=tx) x 16 (p=ty)
#define RP      4                        // p rows per thread
#define NBLOCKS (BATCH * (NPT / TPQ))    // 512
#define EPSF    1e-12f
#define FPSCALE 4294967296.0             // 2^32 fixed point

__device__ unsigned int       g_colmax[BATCH * NPT];   // complement-encoded mins (0 = FLT_MAX)
__device__ unsigned long long g_rowacc;                // fixed-point row-sum accumulator
__device__ unsigned int       g_done;                  // completed-block counter

__global__ __launch_bounds__(NTH, 4)
void chamfer_main(const float* __restrict__ P, const float* __restrict__ G,
                  float* __restrict__ out) {
    const int b     = blockIdx.y;
    const int pbase = blockIdx.x * TPQ;
    const float* Pb = P + (size_t)b * 3 * NPT;
    const float* Gb = G + (size_t)b * 3 * NPT;
    const int tid = threadIdx.x;
    const int tx  = tid & 15;        // g direction
    const int ty  = tid >> 4;        // p direction

    __shared__ float4 sp[TPQ];
    __shared__ float4 sg[2][TGQ];               // double buffer
    __shared__ float  cbuf[2][16][TGQ + 1];     // double buffer, padded
    __shared__ float  sred[NTH];
    __shared__ unsigned int ticket;

    // ---- prologue: prefetch stage-0 gt, load & transform p tile ----
    float rx = 0.f, ry = 0.f, rz = 0.f;
    if (tid < TGQ) {
        rx = Gb[tid];
        ry = Gb[NPT + tid];
        rz = Gb[2 * NPT + tid];
    }
    if (tid < TPQ) {
        float px = Pb[pbase + tid];
        float py = Pb[NPT + pbase + tid];
        float pz = Pb[2 * NPT + pbase + tid];
        sp[tid] = make_float4(-2.f * px, -2.f * py, -2.f * pz,
                              px * px + py * py + pz * pz);
    }
    if (tid < TGQ)
        sg[0][tid] = make_float4(rx, ry, rz, rx * rx + ry * ry + rz * rz);
    __syncthreads();

    float pa[RP], pb_[RP], pc[RP], pp2[RP], rowmin[RP];
#pragma unroll
    for (int ii = 0; ii < RP; ii++) {
        float4 v = sp[ty * RP + ii];
        pa[ii] = v.x; pb_[ii] = v.y; pc[ii] = v.z; pp2[ii] = v.w;
        rowmin[ii] = 3.4e38f;
    }

    for (int s = 0; s < NSTAGES; s++) {
        const int cur = s & 1, nxt = cur ^ 1;

        // issue next-stage gmem loads now; latency hidden under compute
        if (s + 1 < NSTAGES && tid < TGQ) {
            int g = (s + 1) * TGQ + tid;
            rx = Gb[g]; ry = Gb[NPT + g]; rz = Gb[2 * NPT + g];
        }

        // two g-passes of 64 columns each (RG=4) to keep registers small
#pragma unroll
        for (int h = 0; h < 2; h++) {
            float gx[4], gy[4], gz[4], g2[4], colmin[4];
#pragma unroll
            for (int jj = 0; jj < 4; jj++) {
                float4 v = sg[cur][h * 64 + jj * 16 + tx];
                gx[jj] = v.x; gy[jj] = v.y; gz[jj] = v.z; g2[jj] = v.w;
                colmin[jj] = 3.4e38f;
            }

#pragma unroll
            for (int ii = 0; ii < RP; ii++) {
#pragma unroll
                for (int jj = 0; jj < 4; jj++) {
                    float e = fmaf(pc[ii], gz[jj], g2[jj]);
                    e = fmaf(pb_[ii], gy[jj], e);
                    e = fmaf(pa[ii], gx[jj], e);
                    rowmin[ii] = fminf(rowmin[ii], e);
                    colmin[jj] = fminf(colmin[jj], e + pp2[ii]);
                }
            }

            // per-warp column partials (pre-barrier stores)
#pragma unroll
            for (int jj = 0; jj < 4; jj++)
                cbuf[cur][ty][h * 64 + jj * 16 + tx] = colmin[jj];
        }

        // stage s+1 gt chunk -> other smem buffer (prefetch regs landed)
        if (s + 1 < NSTAGES && tid < TGQ)
            sg[nxt][tid] = make_float4(rx, ry, rz, rx * rx + ry * ry + rz * rz);

        __syncthreads();   // the ONLY barrier per stage

        // column reduce overlaps next stage's compute in the other warps
        if (tid < TGQ) {
            float v[16];
#pragma unroll
            for (int t = 0; t < 16; t++) v[t] = cbuf[cur][t][tid];
#pragma unroll
            for (int st = 8; st > 0; st >>= 1)
#pragma unroll
                for (int t = 0; t < 8; t++)
                    if (t < st) v[t] = fminf(v[t], v[t + st]);
            float m = fmaxf(v[0], EPSF);   // clamp (ref); positive bits
            // complement encoding: min(m) == max(0x7f7fffff - bits(m)); init 0 == FLT_MAX
            atomicMax(&g_colmax[b * NPT + s * TGQ + tid],
                      0x7f7fffffu - (unsigned int)__float_as_int(m));
        }
    }

    // row-min reduce across tx: lanes differing in low 4 bits share ty and
    // partition g columns -> xor-shuffle over 1,2,4,8 completes the min.
#pragma unroll
    for (int ii = 0; ii < RP; ii++) {
        float m = rowmin[ii];
#pragma unroll
        for (int off = 1; off < 16; off <<= 1)
            m = fminf(m, __shfl_xor_sync(0xffffffffu, m, off));
        rowmin[ii] = m;
    }

    float rsum = 0.f;
    if (tx == 0) {
#pragma unroll
        for (int ii = 0; ii < RP; ii++)
            rsum += sqrtf(fmaxf(rowmin[ii] + pp2[ii], EPSF));
    }

    sred[tid] = rsum;
    __syncthreads();
    for (int st = NTH / 2; st > 0; st >>= 1) {
        if (tid < st) sred[tid] += sred[tid + st];
        __syncthreads();
    }

    // ---- single-launch epilogue: fixed-point row add, then last block finalizes
    if (tid == 0) {
        unsigned long long fx =
            (unsigned long long)((double)sred[0] * FPSCALE + 0.5);
        atomicAdd(&g_rowacc, fx);          // integer add: commutative => deterministic
        __threadfence();                    // make colmax/rowacc visible before ticket
        ticket = atomicAdd(&g_done, 1u);
    }
    __syncthreads();

    if (ticket == NBLOCKS - 1) {
        // all other blocks have passed their fence. Vectorized gather + reset:
        uint4* cm4 = reinterpret_cast<uint4*>(g_colmax);
        const uint4 z4 = make_uint4(0u, 0u, 0u, 0u);
        float s = 0.f;
#pragma unroll 4
        for (int i = tid; i < (BATCH * NPT) / 4; i += NTH) {
            uint4 c = __ldcg(&cm4[i]);
            s += sqrtf(__int_as_float((int)(0x7f7fffffu - c.x)));
            s += sqrtf(__int_as_float((int)(0x7f7fffffu - c.y)));
            s += sqrtf(__int_as_float((int)(0x7f7fffffu - c.z)));
            s += sqrtf(__int_as_float((int)(0x7f7fffffu - c.w)));
            cm4[i] = z4;                                         // reset for next replay
        }
        sred[tid] = s;
        __syncthreads();
        for (int st = NTH / 2; st > 0; st >>= 1) {
            if (tid < st) sred[tid] += sred[tid + st];
            __syncthreads();
        }
        if (tid == 0) {
            double total = (double)sred[0] + (double)g_rowacc / FPSCALE;
            out[0] = (float)(total / (double)(BATCH * 2 * NPT));  // denom = B*(Np+Ng)
            g_rowacc = 0ull;                                      // reset
            g_done   = 0u;                                        // reset
        }
    }
}

extern "C" void kernel_launch(void* const* d_in, const int* in_sizes, int n_in,
                              void* d_out, int out_size) {
    const float* P = (const float*)d_in[0];
    const float* G = (const float*)d_in[1];

    dim3 grid(NPT / TPQ, BATCH);             // 128 x 4 = 512 blocks, ONE launch
    chamfer_main<<<grid, NTH>>>(P, G, (float*)d_out);
}

// round 13
// speedup vs baseline: 1.0031x; 1.0031x over previous
#include <cuda_runtime.h>
#include <math.h>

// Chamfer loss, B=4, C=3, Np=Ng=8192. R13 = R11 core + g-split 2:
//  512 blocks x 32 stages (same total stage count/overhead as R11's 256x64),
//  occ 3 blocks/SM (24 warps) instead of 2 (16). Stage work stays 128x128
//  (R12 showed shrinking stage work doubles overhead share).
//  - BOTH min sides complement-encoded (atomicMax of 0x7f7fffff - bits):
//    zero-init == FLT_MAX, no init kernel, order-independent => deterministic.
//  - last block (ticket) runs the vectorized finalize and resets globals.

#define BATCH   4
#define NPT     8192
#define TPQ     128                      // predict points per block
#define TGQ     128                      // gt points per stage
#define GSPLIT  2                        // g halves per (batch, p-tile)
#define NSTAGES ((NPT / GSPLIT) / TGQ)   // 32
#define NTH     256                      // 16 (g=tx) x 16 (p=ty)
#define NBLOCKS (BATCH * (NPT / TPQ) * GSPLIT)   // 512
#define EPSF    1e-12f

// [0, B*N)      : col mins (complement bits),  [B*N, 2*B*N): row mins
__device__ unsigned int g_minbuf[2 * BATCH * NPT];
__device__ unsigned int g_done;

__global__ __launch_bounds__(NTH, 3)
void chamfer_main(const float* __restrict__ P, const float* __restrict__ G,
                  float* __restrict__ out) {
    const int b     = blockIdx.z;
    const int pbase = blockIdx.x * TPQ;
    const int gbeg  = blockIdx.y * (NPT / GSPLIT);
    const float* Pb = P + (size_t)b * 3 * NPT;
    const float* Gb = G + (size_t)b * 3 * NPT;
    const int tid = threadIdx.x;
    const int tx  = tid & 15;        // g direction
    const int ty  = tid >> 4;        // p direction

    __shared__ float4 sp[TPQ];
    __shared__ float4 sg[2][TGQ];               // double buffer
    __shared__ float  cbuf[2][16][TGQ + 1];     // double buffer, padded
    __shared__ float  sred[NTH];
    __shared__ unsigned int ticket;

    // ---- prologue: prefetch stage-0 gt, load & transform p tile ----
    float rx = 0.f, ry = 0.f, rz = 0.f;
    if (tid < TGQ) {
        rx = Gb[gbeg + tid];
        ry = Gb[NPT + gbeg + tid];
        rz = Gb[2 * NPT + gbeg + tid];
    }
    if (tid < TPQ) {
        float px = Pb[pbase + tid];
        float py = Pb[NPT + pbase + tid];
        float pz = Pb[2 * NPT + pbase + tid];
        sp[tid] = make_float4(-2.f * px, -2.f * py, -2.f * pz,
                              px * px + py * py + pz * pz);
    }
    if (tid < TGQ)
        sg[0][tid] = make_float4(rx, ry, rz, rx * rx + ry * ry + rz * rz);
    __syncthreads();

    float pa[8], pb_[8], pc[8], pp2[8], rowmin[8];
#pragma unroll
    for (int ii = 0; ii < 8; ii++) {
        float4 v = sp[ty * 8 + ii];
        pa[ii] = v.x; pb_[ii] = v.y; pc[ii] = v.z; pp2[ii] = v.w;
        rowmin[ii] = 3.4e38f;
    }

    for (int s = 0; s < NSTAGES; s++) {
        const int cur = s & 1, nxt = cur ^ 1;

        // issue next-stage gmem loads now; latency hidden under compute
        if (s + 1 < NSTAGES && tid < TGQ) {
            int g = gbeg + (s + 1) * TGQ + tid;
            rx = Gb[g]; ry = Gb[NPT + g]; rz = Gb[2 * NPT + g];
        }

        // two g-passes of 64 columns each (RG=4)
#pragma unroll
        for (int h = 0; h < 2; h++) {
            float gx[4], gy[4], gz[4], g2[4], colmin[4];
#pragma unroll
            for (int jj = 0; jj < 4; jj++) {
                float4 v = sg[cur][h * 64 + jj * 16 + tx];
                gx[jj] = v.x; gy[jj] = v.y; gz[jj] = v.z; g2[jj] = v.w;
                colmin[jj] = 3.4e38f;
            }

#pragma unroll
            for (int ii = 0; ii < 8; ii++) {
#pragma unroll
                for (int jj = 0; jj < 4; jj++) {
                    float e = fmaf(pc[ii], gz[jj], g2[jj]);
                    e = fmaf(pb_[ii], gy[jj], e);
                    e = fmaf(pa[ii], gx[jj], e);
                    rowmin[ii] = fminf(rowmin[ii], e);
                    colmin[jj] = fminf(colmin[jj], e + pp2[ii]);
                }
            }

            // per-warp column partials (pre-barrier stores)
#pragma unroll
            for (int jj = 0; jj < 4; jj++)
                cbuf[cur][ty][h * 64 + jj * 16 + tx] = colmin[jj];
        }

        // stage s+1 gt chunk -> other smem buffer (prefetch regs landed)
        if (s + 1 < NSTAGES && tid < TGQ)
            sg[nxt][tid] = make_float4(rx, ry, rz, rx * rx + ry * ry + rz * rz);

        __syncthreads();   // the ONLY barrier per stage

        // column reduce overlaps next stage's compute in the other warps
        if (tid < TGQ) {
            float v[16];
#pragma unroll
            for (int t = 0; t < 16; t++) v[t] = cbuf[cur][t][tid];
#pragma unroll
            for (int st = 8; st > 0; st >>= 1)
#pragma unroll
                for (int t = 0; t < 8; t++)
                    if (t < st) v[t] = fminf(v[t], v[t + st]);
            float m = fmaxf(v[0], EPSF);   // clamp (ref); positive bits
            atomicMax(&g_minbuf[b * NPT + gbeg + s * TGQ + tid],
                      0x7f7fffffu - (unsigned int)__float_as_int(m));
        }
    }

    // row-min reduce across tx (intra-warp, once), then flush via atomicMax
#pragma unroll
    for (int ii = 0; ii < 8; ii++) {
        float m = rowmin[ii];
#pragma unroll
        for (int off = 1; off < 16; off <<= 1)
            m = fminf(m, __shfl_xor_sync(0xffffffffu, m, off));
        if (tx == 0) {
            m = fmaxf(m + pp2[ii], EPSF);
            atomicMax(&g_minbuf[BATCH * NPT + b * NPT + pbase + ty * 8 + ii],
                      0x7f7fffffu - (unsigned int)__float_as_int(m));
        }
    }

    // ---- single-launch epilogue ----
    __threadfence();        // every thread: its atomics reach L2 before ticket
    __syncthreads();
    if (tid == 0)
        ticket = atomicAdd(&g_done, 1u);
    __syncthreads();

    if (ticket == NBLOCKS - 1) {
        // all blocks done (their fences precede the ticket). Vectorized
        // gather over col+row mins (16k uint4) + reset for graph replay.
        uint4* m4 = reinterpret_cast<uint4*>(g_minbuf);
        const uint4 z4 = make_uint4(0u, 0u, 0u, 0u);
        float s = 0.f;
#pragma unroll 4
        for (int i = tid; i < (2 * BATCH * NPT) / 4; i += NTH) {
            uint4 c = __ldcg(&m4[i]);
            s += sqrtf(__int_as_float((int)(0x7f7fffffu - c.x)));
            s += sqrtf(__int_as_float((int)(0x7f7fffffu - c.y)));
            s += sqrtf(__int_as_float((int)(0x7f7fffffu - c.z)));
            s += sqrtf(__int_as_float((int)(0x7f7fffffu - c.w)));
            m4[i] = z4;                                          // reset
        }
        sred[tid] = s;
        __syncthreads();
        for (int st = NTH / 2; st > 0; st >>= 1) {
            if (tid < st) sred[tid] += sred[tid + st];
            __syncthreads();
        }
        if (tid == 0) {
            out[0] = sred[0] / (float)(BATCH * 2 * NPT);   // denom = B*(Np+Ng)
            g_done = 0u;                                   // reset
        }
    }
}

extern "C" void kernel_launch(void* const* d_in, const int* in_sizes, int n_in,
                              void* d_out, int out_size) {
    const float* P = (const float*)d_in[0];
    const float* G = (const float*)d_in[1];

    dim3 grid(NPT / TPQ, GSPLIT, BATCH);     // 64 x 2 x 4 = 512 blocks, ONE launch
    chamfer_main<<<grid, NTH>>>(P, G, (float*)d_out);
}

// round 14
// speedup vs baseline: 1.0715x; 1.0681x over previous
#include <cuda_runtime.h>
#include <math.h>

// Chamfer loss, B=4, C=3, Np=Ng=8192. R14 = R11 single-launch core with a
// PERFECT-WAVE grid: TPQ=112 -> 74 p-tiles x 4 batches = 296 blocks = exactly
// 2 per SM (148 SMs), single wave, zero idle SMs (R11 left 40 SMs half-idle;
// R12/R13's 512-block grids created second-wave tails).
//  Last tile has 96 dummy rows: loaded as (0,0,0,1e30) so they never win a
//  col-min; their row flush is guarded.
//  - BOTH min sides complement-encoded (atomicMax of 0x7f7fffff - bits):
//    zero-init == FLT_MAX, no init kernel, order-independent => deterministic.
//  - last block (ticket) runs the vectorized finalize and resets globals.

#define BATCH   4
#define NPT     8192
#define TPQ     112                      // predict points per block (74 tiles)
#define NTILES  74
#define RP      7                        // p rows per thread (16*7 = 112)
#define TGQ     128                      // gt points per stage
#define NSTAGES (NPT / TGQ)              // 64
#define NTH     256                      // 16 (g=tx) x 16 (p=ty)
#define NBLOCKS (BATCH * NTILES)         // 296 = 2 * 148
#define EPSF    1e-12f
#define BIGP2   1e30f

// [0, B*N): col mins (complement bits),  [B*N, 2*B*N): row mins
__device__ unsigned int g_minbuf[2 * BATCH * NPT];
__device__ unsigned int g_done;

__global__ __launch_bounds__(NTH, 2)
void chamfer_main(const float* __restrict__ P, const float* __restrict__ G,
                  float* __restrict__ out) {
    const int b     = blockIdx.y;
    const int pbase = blockIdx.x * TPQ;
    const float* Pb = P + (size_t)b * 3 * NPT;
    const float* Gb = G + (size_t)b * 3 * NPT;
    const int tid = threadIdx.x;
    const int tx  = tid & 15;        // g direction
    const int ty  = tid >> 4;        // p direction

    __shared__ float4 sp[TPQ];
    __shared__ float4 sg[2][TGQ];               // double buffer
    __shared__ float  cbuf[2][16][TGQ + 1];     // double buffer, padded
    __shared__ float  sred[NTH];
    __shared__ unsigned int ticket;

    // ---- prologue: prefetch stage-0 gt, load & transform p tile ----
    float rx = 0.f, ry = 0.f, rz = 0.f;
    if (tid < TGQ) {
        rx = Gb[tid];
        ry = Gb[NPT + tid];
        rz = Gb[2 * NPT + tid];
    }
    if (tid < TPQ) {
        int gp = pbase + tid;
        if (gp < NPT) {
            float px = Pb[gp];
            float py = Pb[NPT + gp];
            float pz = Pb[2 * NPT + gp];
            sp[tid] = make_float4(-2.f * px, -2.f * py, -2.f * pz,
                                  px * px + py * py + pz * pz);
        } else {
            sp[tid] = make_float4(0.f, 0.f, 0.f, BIGP2);   // dummy row
        }
    }
    if (tid < TGQ)
        sg[0][tid] = make_float4(rx, ry, rz, rx * rx + ry * ry + rz * rz);
    __syncthreads();

    float pa[RP], pb_[RP], pc[RP], pp2[RP], rowmin[RP];
#pragma unroll
    for (int ii = 0; ii < RP; ii++) {
        float4 v = sp[ty * RP + ii];
        pa[ii] = v.x; pb_[ii] = v.y; pc[ii] = v.z; pp2[ii] = v.w;
        rowmin[ii] = 3.4e38f;
    }

    for (int s = 0; s < NSTAGES; s++) {
        const int cur = s & 1, nxt = cur ^ 1;

        // issue next-stage gmem loads now; latency hidden under compute
        if (s + 1 < NSTAGES && tid < TGQ) {
            int g = (s + 1) * TGQ + tid;
            rx = Gb[g]; ry = Gb[NPT + g]; rz = Gb[2 * NPT + g];
        }

        // two g-passes of 64 columns each (RG=4)
#pragma unroll
        for (int h = 0; h < 2; h++) {
            float gx[4], gy[4], gz[4], g2[4], colmin[4];
#pragma unroll
            for (int jj = 0; jj < 4; jj++) {
                float4 v = sg[cur][h * 64 + jj * 16 + tx];
                gx[jj] = v.x; gy[jj] = v.y; gz[jj] = v.z; g2[jj] = v.w;
                colmin[jj] = 3.4e38f;
            }

#pragma unroll
            for (int ii = 0; ii < RP; ii++) {
#pragma unroll
                for (int jj = 0; jj < 4; jj++) {
                    float e = fmaf(pc[ii], gz[jj], g2[jj]);
                    e = fmaf(pb_[ii], gy[jj], e);
                    e = fmaf(pa[ii], gx[jj], e);
                    rowmin[ii] = fminf(rowmin[ii], e);
                    colmin[jj] = fminf(colmin[jj], e + pp2[ii]);   // dummy: +1e30 never wins
                }
            }

            // per-warp column partials (pre-barrier stores)
#pragma unroll
            for (int jj = 0; jj < 4; jj++)
                cbuf[cur][ty][h * 64 + jj * 16 + tx] = colmin[jj];
        }

        // stage s+1 gt chunk -> other smem buffer (prefetch regs landed)
        if (s + 1 < NSTAGES && tid < TGQ)
            sg[nxt][tid] = make_float4(rx, ry, rz, rx * rx + ry * ry + rz * rz);

        __syncthreads();   // the ONLY barrier per stage

        // column reduce overlaps next stage's compute in the other warps
        if (tid < TGQ) {
            float v[16];
#pragma unroll
            for (int t = 0; t < 16; t++) v[t] = cbuf[cur][t][tid];
#pragma unroll
            for (int st = 8; st > 0; st >>= 1)
#pragma unroll
                for (int t = 0; t < 8; t++)
                    if (t < st) v[t] = fminf(v[t], v[t + st]);
            float m = fmaxf(v[0], EPSF);   // clamp (ref); positive bits
            atomicMax(&g_minbuf[b * NPT + s * TGQ + tid],
                      0x7f7fffffu - (unsigned int)__float_as_int(m));
        }
    }

    // row-min reduce across tx (intra-warp, once), then flush via atomicMax
#pragma unroll
    for (int ii = 0; ii < RP; ii++) {
        float m = rowmin[ii];
#pragma unroll
        for (int off = 1; off < 16; off <<= 1)
            m = fminf(m, __shfl_xor_sync(0xffffffffu, m, off));
        int grow = pbase + ty * RP + ii;
        if (tx == 0 && grow < NPT) {
            m = fmaxf(m + pp2[ii], EPSF);
            atomicMax(&g_minbuf[BATCH * NPT + b * NPT + grow],
                      0x7f7fffffu - (unsigned int)__float_as_int(m));
        }
    }

    // ---- single-launch epilogue ----
    __threadfence();        // every thread: its atomics reach L2 before ticket
    __syncthreads();
    if (tid == 0)
        ticket = atomicAdd(&g_done, 1u);
    __syncthreads();

    if (ticket == NBLOCKS - 1) {
        // all blocks done (their fences precede the ticket). Vectorized
        // gather over col+row mins (16k uint4) + reset for graph replay.
        uint4* m4 = reinterpret_cast<uint4*>(g_minbuf);
        const uint4 z4 = make_uint4(0u, 0u, 0u, 0u);
        float s = 0.f;
#pragma unroll 4
        for (int i = tid; i < (2 * BATCH * NPT) / 4; i += NTH) {
            uint4 c = __ldcg(&m4[i]);
            s += sqrtf(__int_as_float((int)(0x7f7fffffu - c.x)));
            s += sqrtf(__int_as_float((int)(0x7f7fffffu - c.y)));
            s += sqrtf(__int_as_float((int)(0x7f7fffffu - c.z)));
            s += sqrtf(__int_as_float((int)(0x7f7fffffu - c.w)));
            m4[i] = z4;                                          // reset
        }
        sred[tid] = s;
        __syncthreads();
        for (int st = NTH / 2; st > 0; st >>= 1) {
            if (tid < st) sred[tid] += sred[tid + st];
            __syncthreads();
        }
        if (tid == 0) {
            out[0] = sred[0] / (float)(BATCH * 2 * NPT);   // denom = B*(Np+Ng)
            g_done = 0u;                                   // reset
        }
    }
}

extern "C" void kernel_launch(void* const* d_in, const int* in_sizes, int n_in,
                              void* d_out, int out_size) {
    const float* P = (const float*)d_in[0];
    const float* G = (const float*)d_in[1];

    dim3 grid(NTILES, BATCH);                // 74 x 4 = 296 blocks = 2/SM exact
    chamfer_main<<<grid, NTH>>>(P, G, (float*)d_out);
}